// round 15
// baseline (speedup 1.0000x reference)
#include <cuda_runtime.h>
#include <math.h>

#define N_NODES 100000
#define N_EDGES 3200000
#define DIMC 32
#define INDIM 128
#define NGRAPH 250
#define NPER 400
#define KTOP 100
#define TOTALC 97
#define GM_NODES 32
#define GEMM_BLOCKS (N_NODES / GM_NODES)     // 3125
#define FILL_BLOCKS (N_EDGES / 4 / 256)      // 3125
#define BUCKET 128
#define SENT_B (N_NODES * DIMC * 4)          // byte offset of zero sentinel row

// ---------------- device scratch ----------------
__device__ int   g_cnt[N_NODES];               // zeroed by k_zero* each replay (zero-init at load)
__device__ int   g_csr[N_NODES * BUCKET];      // src byte-offset (src*128), padded w/ SENT_B
__device__ float g_dis[N_NODES];
__device__ float g_y0[N_NODES * DIMC + DIMC];  // +1 zero sentinel row (never written)
__device__ float g_x1[N_NODES * DIMC];
__device__ float g_y1[N_NODES * DIMC + DIMC];
__device__ float g_x2[N_NODES * DIMC];
__device__ float g_y2[N_NODES * DIMC + DIMC];
__device__ float g_x3[N_NODES * DIMC];
__device__ float g_score[N_NODES];
__device__ float g_c2f[NGRAPH * 2944];

// ---------------- g_cnt zeroing, split into thirds (also pads launch index) ----------------
#define ZCHUNK 33344                           // 33344*3 >= 100000; 33344/256 = 130.25 -> 131 blocks
__global__ void k_zero(int part) {
    int i = part * ZCHUNK + blockIdx.x * 256 + threadIdx.x;
    if (i < N_NODES && i < (part + 1) * ZCHUNK) g_cnt[i] = 0;
}

// ---------------- fused build: sequential roles ----------------
// blocks [0, GEMM_BLOCKS): GEMM tile (raw h = X@W1); rest: histogram+CSR fill.
__global__ void __launch_bounds__(256) k_build(const float* __restrict__ X,
                                               const float* __restrict__ W,
                                               const int* __restrict__ src,
                                               const int* __restrict__ dst) {
    __shared__ float Xs[GM_NODES * INDIM];   // 16 KB
    __shared__ float Ws[INDIM * DIMC];       // 16 KB
    int tid = threadIdx.x;

    if (blockIdx.x >= GEMM_BLOCKS) {
        // ---- fill: histogram + CSR in one pass (4 edges/thread, int4) ----
        int t4 = (blockIdx.x - GEMM_BLOCKS) * 256 + tid;
        int4 s = reinterpret_cast<const int4*>(src)[t4];
        int4 d = reinterpret_cast<const int4*>(dst)[t4];
        int r0 = atomicAdd(&g_cnt[d.x], 1);
        int r1 = atomicAdd(&g_cnt[d.y], 1);
        int r2 = atomicAdd(&g_cnt[d.z], 1);
        int r3 = atomicAdd(&g_cnt[d.w], 1);
        g_csr[(d.x << 7) + r0] = s.x << 7;   // byte offset of src row
        g_csr[(d.y << 7) + r1] = s.y << 7;
        g_csr[(d.z << 7) + r2] = s.z << 7;
        g_csr[(d.w << 7) + r3] = s.w << 7;
        return;
    }

    // ---- GEMM: 32 nodes x 32 dims, 4 outputs/thread (raw, unscaled) ----
    int nbase = blockIdx.x * GM_NODES;
    const float4* Wg = reinterpret_cast<const float4*>(W);
    float4* Ws4 = reinterpret_cast<float4*>(Ws);
    for (int i = tid; i < INDIM * DIMC / 4; i += 256) Ws4[i] = Wg[i];
    const float4* Xg = reinterpret_cast<const float4*>(X) + (size_t)nbase * (INDIM / 4);
    float4* Xs4 = reinterpret_cast<float4*>(Xs);
    for (int i = tid; i < GM_NODES * INDIM / 4; i += 256) Xs4[i] = Xg[i];
    __syncthreads();

    int dim = tid & 31, nq = tid >> 5;       // nq = 0..7 -> nodes nq*4..nq*4+3
    const float* xr0 = Xs + (nq * 4 + 0) * INDIM;
    const float* xr1 = Xs + (nq * 4 + 1) * INDIM;
    const float* xr2 = Xs + (nq * 4 + 2) * INDIM;
    const float* xr3 = Xs + (nq * 4 + 3) * INDIM;
    float a0 = 0.f, a1 = 0.f, a2 = 0.f, a3 = 0.f;
#pragma unroll 4
    for (int kb = 0; kb < INDIM; kb += 4) {
        float w0 = Ws[(kb + 0) * DIMC + dim];
        float w1 = Ws[(kb + 1) * DIMC + dim];
        float w2 = Ws[(kb + 2) * DIMC + dim];
        float w3 = Ws[(kb + 3) * DIMC + dim];
        float4 v0 = *reinterpret_cast<const float4*>(xr0 + kb);
        float4 v1 = *reinterpret_cast<const float4*>(xr1 + kb);
        float4 v2 = *reinterpret_cast<const float4*>(xr2 + kb);
        float4 v3 = *reinterpret_cast<const float4*>(xr3 + kb);
        a0 = fmaf(v0.x, w0, a0); a0 = fmaf(v0.y, w1, a0);
        a0 = fmaf(v0.z, w2, a0); a0 = fmaf(v0.w, w3, a0);
        a1 = fmaf(v1.x, w0, a1); a1 = fmaf(v1.y, w1, a1);
        a1 = fmaf(v1.z, w2, a1); a1 = fmaf(v1.w, w3, a1);
        a2 = fmaf(v2.x, w0, a2); a2 = fmaf(v2.y, w1, a2);
        a2 = fmaf(v2.z, w2, a2); a2 = fmaf(v2.w, w3, a2);
        a3 = fmaf(v3.x, w0, a3); a3 = fmaf(v3.y, w1, a3);
        a3 = fmaf(v3.z, w2, a3); a3 = fmaf(v3.w, w3, a3);
    }
    int nb = nbase + nq * 4;
    g_y0[(nb + 0) * DIMC + dim] = a0;
    g_y0[(nb + 1) * DIMC + dim] = a1;
    g_y0[(nb + 2) * DIMC + dim] = a2;
    g_y0[(nb + 3) * DIMC + dim] = a3;
}

// ---------------- y0 *= dis; store dis; pad buckets to multiple of 8 ----------------
__global__ void k_y0() {
    int node = blockIdx.x * 8 + (threadIdx.x >> 5);
    if (node >= N_NODES) return;
    int lane = threadIdx.x & 31;
    int c = g_cnt[node];
    float d = rsqrtf((float)c + 1.0f);
    if (lane == 0) g_dis[node] = d;
    g_y0[node * DIMC + lane] *= d;
    int p = (c + 7) & ~7;
    if (c + lane < p) g_csr[(node << 7) + c + lane] = SENT_B;
}

// ---------------- bucket gather (pad-8; ldcg rows, ldcs csr) + fused transform ----------------
__global__ void __launch_bounds__(256) k_gather(int layer, const float* __restrict__ W,
                         const float* __restrict__ b,
                         const float* __restrict__ W4, const float* __restrict__ b4) {
    __shared__ float Ws[DIMC * DIMC];
    int tid = threadIdx.x;
    if (layer >= 2) {
        for (int i = tid; i < DIMC * DIMC; i += 256) Ws[i] = W[i];
        __syncthreads();
    }
    const float* __restrict__ Y = (layer == 1) ? g_y0 : (layer == 2 ? g_y1 : g_y2);
    const char* __restrict__ Yb = reinterpret_cast<const char*>(Y);
    int node = blockIdx.x * 8 + (tid >> 5);
    if (node >= N_NODES) return;
    int lane = tid & 31;
    int grp = lane >> 3, sub = lane & 7;
    int sub16 = sub * 16;
    int sub4 = sub * 4;
    int beg = node << 7;
    int p8 = (g_cnt[node] + 7) & ~7;
    int end16 = beg + (p8 & ~15);

    float4 acc = make_float4(0.f, 0.f, 0.f, 0.f);
    for (int base = beg; base < end16; base += 16) {
        int4 si = __ldcs(reinterpret_cast<const int4*>(&g_csr[base + grp * 4]));
        const float4 v0 = __ldcg(reinterpret_cast<const float4*>(Yb + si.x + sub16));
        const float4 v1 = __ldcg(reinterpret_cast<const float4*>(Yb + si.y + sub16));
        const float4 v2 = __ldcg(reinterpret_cast<const float4*>(Yb + si.z + sub16));
        const float4 v3 = __ldcg(reinterpret_cast<const float4*>(Yb + si.w + sub16));
        acc.x += (v0.x + v1.x) + (v2.x + v3.x);
        acc.y += (v0.y + v1.y) + (v2.y + v3.y);
        acc.z += (v0.z + v1.z) + (v2.z + v3.z);
        acc.w += (v0.w + v1.w) + (v2.w + v3.w);
    }
    if (p8 & 8) {
        int2 si = __ldcs(reinterpret_cast<const int2*>(&g_csr[end16 + grp * 2]));
        const float4 v0 = __ldcg(reinterpret_cast<const float4*>(Yb + si.x + sub16));
        const float4 v1 = __ldcg(reinterpret_cast<const float4*>(Yb + si.y + sub16));
        acc.x += v0.x + v1.x;
        acc.y += v0.y + v1.y;
        acc.z += v0.z + v1.z;
        acc.w += v0.w + v1.w;
    }
#pragma unroll
    for (int off = 8; off <= 16; off <<= 1) {
        acc.x += __shfl_xor_sync(0xffffffffu, acc.x, off);
        acc.y += __shfl_xor_sync(0xffffffffu, acc.y, off);
        acc.z += __shfl_xor_sync(0xffffffffu, acc.z, off);
        acc.w += __shfl_xor_sync(0xffffffffu, acc.w, off);
    }
    float dis = g_dis[node];
    const float4 yself = *reinterpret_cast<const float4*>(Yb + (node << 7) + sub16);
    acc.x = (acc.x + yself.x) * dis;
    acc.y = (acc.y + yself.y) * dis;
    acc.z = (acc.z + yself.z) * dis;
    acc.w = (acc.w + yself.w) * dis;

    if (layer == 1) {
        if (grp == 0) {
            float4 o;
            o.x = tanhf(acc.x + b[sub4 + 0]);
            o.y = tanhf(acc.y + b[sub4 + 1]);
            o.z = tanhf(acc.z + b[sub4 + 2]);
            o.w = tanhf(acc.w + b[sub4 + 3]);
            *reinterpret_cast<float4*>(&g_x1[node * DIMC + sub4]) = o;
            float4 y;
            y.x = o.x * dis; y.y = o.y * dis; y.z = o.z * dis; y.w = o.w * dis;
            *reinterpret_cast<float4*>(&g_y1[node * DIMC + sub4]) = y;
        }
        return;
    }

    float outacc = 0.0f;
#pragma unroll
    for (int jb = 0; jb < 8; jb++) {
        float z0 = __shfl_sync(0xffffffffu, acc.x, jb);
        float z1 = __shfl_sync(0xffffffffu, acc.y, jb);
        float z2 = __shfl_sync(0xffffffffu, acc.z, jb);
        float z3 = __shfl_sync(0xffffffffu, acc.w, jb);
        outacc = fmaf(z0, Ws[(jb * 4 + 0) * DIMC + lane], outacc);
        outacc = fmaf(z1, Ws[(jb * 4 + 1) * DIMC + lane], outacc);
        outacc = fmaf(z2, Ws[(jb * 4 + 2) * DIMC + lane], outacc);
        outacc = fmaf(z3, Ws[(jb * 4 + 3) * DIMC + lane], outacc);
    }
    float o = tanhf(outacc + b[lane]);
    if (layer == 2) {
        g_x2[node * DIMC + lane] = o;
        g_y2[node * DIMC + lane] = o * dis;
    } else {
        g_x3[node * DIMC + lane] = o;
        float t = acc.x * W4[sub4 + 0] + acc.y * W4[sub4 + 1]
                + acc.z * W4[sub4 + 2] + acc.w * W4[sub4 + 3];
        t += __shfl_xor_sync(0xffffffffu, t, 1);
        t += __shfl_xor_sync(0xffffffffu, t, 2);
        t += __shfl_xor_sync(0xffffffffu, t, 4);
        if (lane == 0) g_score[node] = tanhf(t + b4[0]);
    }
}

// ---------------- fused tail: sortpool -> conv1+pool -> conv2 ----------------
__global__ void __launch_bounds__(256) k_tail(const float* __restrict__ cw1,
                                              const float* __restrict__ cb1,
                                              const float* __restrict__ cw2,
                                              const float* __restrict__ cb2) {
    __shared__ float s[512];
    __shared__ int   si[512];
    __shared__ float xs[KTOP * TOTALC];   // reused as ps (128*50)
    int g = blockIdx.x, tid = threadIdx.x;

    for (int i = tid; i < 512; i += 256) {
        if (i < NPER) { s[i] = g_score[g * NPER + i]; si[i] = i; }
        else          { s[i] = __int_as_float(0xff800000); si[i] = 0x7FFFFFFF; }
    }
    __syncthreads();
    for (int k = 2; k <= 512; k <<= 1) {
        for (int j = k >> 1; j > 0; j >>= 1) {
            for (int i = tid; i < 512; i += 256) {
                int ixj = i ^ j;
                if (ixj > i) {
                    float a = s[i], bb = s[ixj];
                    int ia = si[i], ib = si[ixj];
                    bool before = (a > bb) || (a == bb && ia < ib);
                    bool dirDesc = ((i & k) == 0);
                    if (dirDesc ? !before : before) {
                        s[i] = bb; s[ixj] = a; si[i] = ib; si[ixj] = ia;
                    }
                }
            }
            __syncthreads();
        }
    }

    for (int i = tid; i < KTOP * TOTALC; i += 256) {
        int kslot = i / TOTALC, t = i - kslot * TOTALC;
        int n = g * NPER + si[kslot];
        float v;
        if (t < 32)      v = g_x1[n * DIMC + t];
        else if (t < 64) v = g_x2[n * DIMC + t - 32];
        else if (t < 96) v = g_x3[n * DIMC + t - 64];
        else             v = g_score[n];
        xs[i] = v;
    }
    __syncthreads();

    float pr[28];
    int nit = 0;
    for (int item = tid; item < 32 * 50; item += 256, nit++) {
        int cb = item / 50, j = item - cb * 50;
        const float* r0 = xs + (2 * j) * TOTALC;
        const float* r1 = r0 + TOTALC;
        float a[8];
#pragma unroll
        for (int q = 0; q < 4; q++) { float bb = cb1[cb + q * 32]; a[q] = bb; a[4 + q] = bb; }
#pragma unroll 2
        for (int t = 0; t < TOTALC; t++) {
            float v0 = r0[t], v1 = r1[t];
#pragma unroll
            for (int q = 0; q < 4; q++) {
                float wv = cw1[(cb + q * 32) * TOTALC + t];
                a[q]     = fmaf(v0, wv, a[q]);
                a[4 + q] = fmaf(v1, wv, a[4 + q]);
            }
        }
#pragma unroll
        for (int q = 0; q < 4; q++)
            pr[nit * 4 + q] = fmaxf(fmaxf(a[q], a[4 + q]), 0.0f);
    }
    __syncthreads();
    float* ps = xs;
    nit = 0;
    for (int item = tid; item < 32 * 50; item += 256, nit++) {
        int cb = item / 50, j = item - cb * 50;
#pragma unroll
        for (int q = 0; q < 4; q++)
            ps[(cb + q * 32) * 50 + j] = pr[nit * 4 + q];
    }
    __syncthreads();

    for (int item = tid; item < 16 * 46; item += 256) {
        int ob = item / 46, j = item - ob * 46;
        float a0 = cb2[ob], a1 = cb2[ob + 16], a2 = cb2[ob + 32], a3 = cb2[ob + 48];
        const float* w0 = cw2 + (ob)      * 640;
        const float* w1 = cw2 + (ob + 16) * 640;
        const float* w2 = cw2 + (ob + 32) * 640;
        const float* w3 = cw2 + (ob + 48) * 640;
#pragma unroll 2
        for (int i = 0; i < 128; i++) {
            const float* pp = ps + i * 50 + j;
            float p0 = pp[0], p1 = pp[1], p2 = pp[2], p3 = pp[3], p4 = pp[4];
            const float* q0 = w0 + i * 5;
            const float* q1 = w1 + i * 5;
            const float* q2 = w2 + i * 5;
            const float* q3 = w3 + i * 5;
            a0 = fmaf(p0, q0[0], a0); a0 = fmaf(p1, q0[1], a0); a0 = fmaf(p2, q0[2], a0);
            a0 = fmaf(p3, q0[3], a0); a0 = fmaf(p4, q0[4], a0);
            a1 = fmaf(p0, q1[0], a1); a1 = fmaf(p1, q1[1], a1); a1 = fmaf(p2, q1[2], a1);
            a1 = fmaf(p3, q1[3], a1); a1 = fmaf(p4, q1[4], a1);
            a2 = fmaf(p0, q2[0], a2); a2 = fmaf(p1, q2[1], a2); a2 = fmaf(p2, q2[2], a2);
            a2 = fmaf(p3, q2[3], a2); a2 = fmaf(p4, q2[4], a2);
            a3 = fmaf(p0, q3[0], a3); a3 = fmaf(p1, q3[1], a3); a3 = fmaf(p2, q3[2], a3);
            a3 = fmaf(p3, q3[3], a3); a3 = fmaf(p4, q3[4], a3);
        }
        g_c2f[g * 2944 + (ob)      * 46 + j] = fmaxf(a0, 0.0f);
        g_c2f[g * 2944 + (ob + 16) * 46 + j] = fmaxf(a1, 0.0f);
        g_c2f[g * 2944 + (ob + 32) * 46 + j] = fmaxf(a2, 0.0f);
        g_c2f[g * 2944 + (ob + 48) * 46 + j] = fmaxf(a3, 0.0f);
    }
}

// ---------------- fc1 + relu + fc3 + log_softmax ----------------
__global__ void __launch_bounds__(256) k_fc(const float* __restrict__ fw1,
                                            const float* __restrict__ fb1,
                                            const float* __restrict__ fw3,
                                            const float* __restrict__ fb3,
                                            float* __restrict__ out) {
    __shared__ float cs[4 * 2944];
    __shared__ float part[256];
    int gb = blockIdx.x, tid = threadIdx.x;
    int g0 = gb * 4;
    for (int i = tid; i < 4 * 2944; i += 256) {
        int g = g0 + i / 2944;
        cs[i] = (g < NGRAPH) ? g_c2f[g * 2944 + (i % 2944)] : 0.0f;
    }
    __syncthreads();
    int half = tid >> 7;
    int o    = tid & 127;
    int dbeg = half * 368;
    const float4* wr = reinterpret_cast<const float4*>(fw1 + (size_t)o * 2944) + dbeg;
    const float4* c0 = reinterpret_cast<const float4*>(cs) + dbeg;
    const float4* c1 = reinterpret_cast<const float4*>(cs + 2944) + dbeg;
    const float4* c2 = reinterpret_cast<const float4*>(cs + 2 * 2944) + dbeg;
    const float4* c3 = reinterpret_cast<const float4*>(cs + 3 * 2944) + dbeg;
    float a0 = 0, a1 = 0, a2 = 0, a3 = 0;
    for (int d = 0; d < 368; d++) {
        float4 w = wr[d];
        float4 v;
        v = c0[d]; a0 += w.x * v.x + w.y * v.y + w.z * v.z + w.w * v.w;
        v = c1[d]; a1 += w.x * v.x + w.y * v.y + w.z * v.z + w.w * v.w;
        v = c2[d]; a2 += w.x * v.x + w.y * v.y + w.z * v.z + w.w * v.w;
        v = c3[d]; a3 += w.x * v.x + w.y * v.y + w.z * v.z + w.w * v.w;
    }
    if (half == 1) { part[o] = a0; part[o + 128] = a1; }
    __syncthreads();
    if (half == 0) { a0 += part[o]; a1 += part[o + 128]; }
    __syncthreads();
    if (half == 1) { part[o] = a2; part[o + 128] = a3; }
    __syncthreads();
    if (half == 0) {
        a2 += part[o]; a3 += part[o + 128];
        float bb = fb1[o];
        cs[0 * 128 + o] = fmaxf(a0 + bb, 0.0f);
        cs[1 * 128 + o] = fmaxf(a1 + bb, 0.0f);
        cs[2 * 128 + o] = fmaxf(a2 + bb, 0.0f);
        cs[3 * 128 + o] = fmaxf(a3 + bb, 0.0f);
    }
    __syncthreads();
    int wid = tid >> 5, lane = tid & 31;
    if (wid < 4 && g0 + wid < NGRAPH) {
        float l0 = 0.f, l1 = 0.f;
#pragma unroll
        for (int k = 0; k < 4; k++) {
            int d = lane + 32 * k;
            float h = cs[wid * 128 + d];
            l0 = fmaf(h, fw3[d], l0);
            l1 = fmaf(h, fw3[128 + d], l1);
        }
#pragma unroll
        for (int off = 16; off; off >>= 1) {
            l0 += __shfl_xor_sync(0xffffffffu, l0, off);
            l1 += __shfl_xor_sync(0xffffffffu, l1, off);
        }
        if (lane == 0) {
            l0 += fb3[0]; l1 += fb3[1];
            float m = fmaxf(l0, l1);
            float lse = m + logf(expf(l0 - m) + expf(l1 - m));
            out[(g0 + wid) * 2 + 0] = l0 - lse;
            out[(g0 + wid) * 2 + 1] = l1 - lse;
        }
    }
}

// ---------------- launch ----------------
extern "C" void kernel_launch(void* const* d_in, const int* in_sizes, int n_in,
                              void* d_out, int out_size) {
    const float* x   = (const float*)d_in[0];
    const int*   ei  = (const int*)d_in[1];
    const int*   src = ei;
    const int*   dst = ei + N_EDGES;
    const float* W1 = (const float*)d_in[3];  const float* b1 = (const float*)d_in[4];
    const float* W2 = (const float*)d_in[5];  const float* b2 = (const float*)d_in[6];
    const float* W3 = (const float*)d_in[7];  const float* b3 = (const float*)d_in[8];
    const float* W4 = (const float*)d_in[9];  const float* b4 = (const float*)d_in[10];
    const float* cw1 = (const float*)d_in[11]; const float* cb1 = (const float*)d_in[12];
    const float* cw2 = (const float*)d_in[13]; const float* cb2 = (const float*)d_in[14];
    const float* fw1 = (const float*)d_in[15]; const float* fb1 = (const float*)d_in[16];
    const float* fw3 = (const float*)d_in[17]; const float* fb3 = (const float*)d_in[18];
    float* out = (float*)d_out;

    const int TB = 256;
    const int gG8 = (N_NODES + 7) / 8;           // 12500
    const int gZ  = (ZCHUNK + TB - 1) / TB;      // 131

    k_zero<<<gZ, TB>>>(0);                                        // 0
    k_zero<<<gZ, TB>>>(1);                                        // 1
    k_zero<<<gZ, TB>>>(2);                                        // 2
    k_build<<<GEMM_BLOCKS + FILL_BLOCKS, TB>>>(x, W1, src, dst);  // 3 <- profiled
    k_y0<<<gG8, TB>>>();                                          // 4 (dis, scale, pad8)
    k_gather<<<gG8, TB>>>(1, nullptr, b1, nullptr, nullptr);      // 5
    k_gather<<<gG8, TB>>>(2, W2, b2, nullptr, nullptr);           // 6
    k_gather<<<gG8, TB>>>(3, W3, b3, W4, b4);                     // 7
    k_tail<<<NGRAPH, TB>>>(cw1, cb1, cw2, cb2);                   // 8
    k_fc<<<(NGRAPH + 3) / 4, TB>>>(fw1, fb1, fw3, fb3, out);      // 9
}

// round 16
// speedup vs baseline: 1.1034x; 1.1034x over previous
#include <cuda_runtime.h>
#include <math.h>

#define N_NODES 100000
#define N_EDGES 3200000
#define DIMC 32
#define INDIM 128
#define NGRAPH 250
#define NPER 400
#define KTOP 100
#define TOTALC 97
#define GM1_NODES 64
#define BUCKET 128
#define SENT (N_NODES * DIMC)

// ---------------- device scratch ----------------
__device__ int   g_cnt[N_NODES];               // zeroed by k_fc (zero-init at load)
__device__ int   g_csr[N_NODES * BUCKET];      // src*32, bucket per node, padded to 8 w/ SENT
__device__ float g_dis[N_NODES];
__device__ float g_y0[N_NODES * DIMC + DIMC];  // +1 zero sentinel row
__device__ float g_x1[N_NODES * DIMC];
__device__ float g_y1[N_NODES * DIMC + DIMC];
__device__ float g_x2[N_NODES * DIMC];
__device__ float g_y2[N_NODES * DIMC + DIMC];
__device__ float g_x3[N_NODES * DIMC];
__device__ float g_score[N_NODES];
__device__ float g_c2f[NGRAPH * 2944];

// ---------------- single-pass bucket fill (histogram + CSR in one) ----------------
__global__ void k_fillb(const int* __restrict__ src, const int* __restrict__ dst) {
    int t4 = blockIdx.x * 256 + threadIdx.x;
    if (t4 < N_EDGES / 4) {
        int4 s = reinterpret_cast<const int4*>(src)[t4];
        int4 d = reinterpret_cast<const int4*>(dst)[t4];
        int r0 = atomicAdd(&g_cnt[d.x], 1);
        int r1 = atomicAdd(&g_cnt[d.y], 1);
        int r2 = atomicAdd(&g_cnt[d.z], 1);
        int r3 = atomicAdd(&g_cnt[d.w], 1);
        g_csr[(d.x << 7) + r0] = s.x << 5;
        g_csr[(d.y << 7) + r1] = s.y << 5;
        g_csr[(d.z << 7) + r2] = s.z << 5;
        g_csr[(d.w << 7) + r3] = s.w << 5;
    }
}

// ---------------- y0 = dis * (X @ W1); computes dis; pads buckets to align8 ----------------
__global__ void __launch_bounds__(256) k_gemm1(const float* __restrict__ X,
                                               const float* __restrict__ W) {
    __shared__ float Xs[GM1_NODES * INDIM];  // 32 KB
    __shared__ float Ws[INDIM * DIMC];       // 16 KB
    int tid = threadIdx.x;
    int nbase = blockIdx.x * GM1_NODES;

    // pad sentinels for this block's nodes (fillb completed; counts final)
    if (tid < GM1_NODES) {
        int n = nbase + tid;
        if (n < N_NODES) {
            int c = g_cnt[n];
            int p = (c + 7) & ~7;
            int base = n << 7;
            for (int j = c; j < p; j++) g_csr[base + j] = SENT;
        }
    }

    const float4* Wg = reinterpret_cast<const float4*>(W);
    float4* Ws4 = reinterpret_cast<float4*>(Ws);
    for (int i = tid; i < INDIM * DIMC / 4; i += 256) Ws4[i] = Wg[i];
    const float4* Xg = reinterpret_cast<const float4*>(X) + (size_t)nbase * (INDIM / 4);
    float4* Xs4 = reinterpret_cast<float4*>(Xs);
    for (int i = tid; i < GM1_NODES * INDIM / 4; i += 256) {
        int row = nbase + (i >> 5);
        Xs4[i] = (row < N_NODES) ? Xg[i] : make_float4(0.f, 0.f, 0.f, 0.f);
    }
    __syncthreads();

    int dp = tid & 15;          // dim pair -> dims 2dp, 2dp+1
    int ng = tid >> 4;          // node group 0..15 -> nodes ng*4..ng*4+3
    const float* x0 = Xs + (ng * 4 + 0) * INDIM;
    const float* x1 = Xs + (ng * 4 + 1) * INDIM;
    const float* x2 = Xs + (ng * 4 + 2) * INDIM;
    const float* x3 = Xs + (ng * 4 + 3) * INDIM;
    float a[8] = {0.f, 0.f, 0.f, 0.f, 0.f, 0.f, 0.f, 0.f};
#pragma unroll 4
    for (int k = 0; k < INDIM; k += 4) {
        float2 w0 = *reinterpret_cast<const float2*>(Ws + (k + 0) * DIMC + dp * 2);
        float2 w1 = *reinterpret_cast<const float2*>(Ws + (k + 1) * DIMC + dp * 2);
        float2 w2 = *reinterpret_cast<const float2*>(Ws + (k + 2) * DIMC + dp * 2);
        float2 w3 = *reinterpret_cast<const float2*>(Ws + (k + 3) * DIMC + dp * 2);
        float4 v;
        v = *reinterpret_cast<const float4*>(x0 + k);
        a[0] = fmaf(v.x, w0.x, a[0]); a[0] = fmaf(v.y, w1.x, a[0]);
        a[0] = fmaf(v.z, w2.x, a[0]); a[0] = fmaf(v.w, w3.x, a[0]);
        a[1] = fmaf(v.x, w0.y, a[1]); a[1] = fmaf(v.y, w1.y, a[1]);
        a[1] = fmaf(v.z, w2.y, a[1]); a[1] = fmaf(v.w, w3.y, a[1]);
        v = *reinterpret_cast<const float4*>(x1 + k);
        a[2] = fmaf(v.x, w0.x, a[2]); a[2] = fmaf(v.y, w1.x, a[2]);
        a[2] = fmaf(v.z, w2.x, a[2]); a[2] = fmaf(v.w, w3.x, a[2]);
        a[3] = fmaf(v.x, w0.y, a[3]); a[3] = fmaf(v.y, w1.y, a[3]);
        a[3] = fmaf(v.z, w2.y, a[3]); a[3] = fmaf(v.w, w3.y, a[3]);
        v = *reinterpret_cast<const float4*>(x2 + k);
        a[4] = fmaf(v.x, w0.x, a[4]); a[4] = fmaf(v.y, w1.x, a[4]);
        a[4] = fmaf(v.z, w2.x, a[4]); a[4] = fmaf(v.w, w3.x, a[4]);
        a[5] = fmaf(v.x, w0.y, a[5]); a[5] = fmaf(v.y, w1.y, a[5]);
        a[5] = fmaf(v.z, w2.y, a[5]); a[5] = fmaf(v.w, w3.y, a[5]);
        v = *reinterpret_cast<const float4*>(x3 + k);
        a[6] = fmaf(v.x, w0.x, a[6]); a[6] = fmaf(v.y, w1.x, a[6]);
        a[6] = fmaf(v.z, w2.x, a[6]); a[6] = fmaf(v.w, w3.x, a[6]);
        a[7] = fmaf(v.x, w0.y, a[7]); a[7] = fmaf(v.y, w1.y, a[7]);
        a[7] = fmaf(v.z, w2.y, a[7]); a[7] = fmaf(v.w, w3.y, a[7]);
    }
#pragma unroll
    for (int q = 0; q < 4; q++) {
        int n = nbase + ng * 4 + q;
        if (n < N_NODES) {
            float d = rsqrtf((float)g_cnt[n] + 1.0f);
            if (dp == 0) g_dis[n] = d;
            *reinterpret_cast<float2*>(&g_y0[n * DIMC + dp * 2]) =
                make_float2(a[2 * q] * d, a[2 * q + 1] * d);
        }
    }
}

// ---------------- bucket gather (pad-8: int4 main loop + int2 tail) + fused transform ----------------
__global__ void __launch_bounds__(256) k_gather(int layer, const float* __restrict__ W,
                         const float* __restrict__ b,
                         const float* __restrict__ W4, const float* __restrict__ b4) {
    __shared__ float Ws[DIMC * DIMC];
    int tid = threadIdx.x;
    if (layer >= 2) {
        for (int i = tid; i < DIMC * DIMC; i += 256) Ws[i] = W[i];
        __syncthreads();
    }
    const float* __restrict__ Y = (layer == 1) ? g_y0 : (layer == 2 ? g_y1 : g_y2);
    int node = blockIdx.x * 8 + (tid >> 5);
    if (node >= N_NODES) return;
    int lane = tid & 31;
    int grp = lane >> 3, sub = lane & 7;
    int sub4 = sub * 4;
    int beg = node << 7;
    int p8 = (g_cnt[node] + 7) & ~7;
    int end16 = beg + (p8 & ~15);

    float4 acc = make_float4(0.f, 0.f, 0.f, 0.f);
    for (int base = beg; base < end16; base += 16) {
        int4 si = *reinterpret_cast<const int4*>(&g_csr[base + grp * 4]);
        const float4 v0 = *reinterpret_cast<const float4*>(Y + si.x + sub4);
        const float4 v1 = *reinterpret_cast<const float4*>(Y + si.y + sub4);
        const float4 v2 = *reinterpret_cast<const float4*>(Y + si.z + sub4);
        const float4 v3 = *reinterpret_cast<const float4*>(Y + si.w + sub4);
        acc.x += (v0.x + v1.x) + (v2.x + v3.x);
        acc.y += (v0.y + v1.y) + (v2.y + v3.y);
        acc.z += (v0.z + v1.z) + (v2.z + v3.z);
        acc.w += (v0.w + v1.w) + (v2.w + v3.w);
    }
    if (p8 & 8) {
        int2 si = *reinterpret_cast<const int2*>(&g_csr[end16 + grp * 2]);
        const float4 v0 = *reinterpret_cast<const float4*>(Y + si.x + sub4);
        const float4 v1 = *reinterpret_cast<const float4*>(Y + si.y + sub4);
        acc.x += v0.x + v1.x;
        acc.y += v0.y + v1.y;
        acc.z += v0.z + v1.z;
        acc.w += v0.w + v1.w;
    }
#pragma unroll
    for (int off = 8; off <= 16; off <<= 1) {
        acc.x += __shfl_xor_sync(0xffffffffu, acc.x, off);
        acc.y += __shfl_xor_sync(0xffffffffu, acc.y, off);
        acc.z += __shfl_xor_sync(0xffffffffu, acc.z, off);
        acc.w += __shfl_xor_sync(0xffffffffu, acc.w, off);
    }
    float dis = g_dis[node];
    const float4 yself = *reinterpret_cast<const float4*>(Y + node * DIMC + sub4);
    acc.x = (acc.x + yself.x) * dis;
    acc.y = (acc.y + yself.y) * dis;
    acc.z = (acc.z + yself.z) * dis;
    acc.w = (acc.w + yself.w) * dis;

    if (layer == 1) {
        if (grp == 0) {
            float4 o;
            o.x = tanhf(acc.x + b[sub4 + 0]);
            o.y = tanhf(acc.y + b[sub4 + 1]);
            o.z = tanhf(acc.z + b[sub4 + 2]);
            o.w = tanhf(acc.w + b[sub4 + 3]);
            *reinterpret_cast<float4*>(&g_x1[node * DIMC + sub4]) = o;
            float4 y;
            y.x = o.x * dis; y.y = o.y * dis; y.z = o.z * dis; y.w = o.w * dis;
            *reinterpret_cast<float4*>(&g_y1[node * DIMC + sub4]) = y;
        }
        return;
    }

    float outacc = 0.0f;
#pragma unroll
    for (int jb = 0; jb < 8; jb++) {
        float z0 = __shfl_sync(0xffffffffu, acc.x, jb);
        float z1 = __shfl_sync(0xffffffffu, acc.y, jb);
        float z2 = __shfl_sync(0xffffffffu, acc.z, jb);
        float z3 = __shfl_sync(0xffffffffu, acc.w, jb);
        outacc = fmaf(z0, Ws[(jb * 4 + 0) * DIMC + lane], outacc);
        outacc = fmaf(z1, Ws[(jb * 4 + 1) * DIMC + lane], outacc);
        outacc = fmaf(z2, Ws[(jb * 4 + 2) * DIMC + lane], outacc);
        outacc = fmaf(z3, Ws[(jb * 4 + 3) * DIMC + lane], outacc);
    }
    float o = tanhf(outacc + b[lane]);
    if (layer == 2) {
        g_x2[node * DIMC + lane] = o;
        g_y2[node * DIMC + lane] = o * dis;
    } else {
        g_x3[node * DIMC + lane] = o;
        float t = acc.x * W4[sub4 + 0] + acc.y * W4[sub4 + 1]
                + acc.z * W4[sub4 + 2] + acc.w * W4[sub4 + 3];
        t += __shfl_xor_sync(0xffffffffu, t, 1);
        t += __shfl_xor_sync(0xffffffffu, t, 2);
        t += __shfl_xor_sync(0xffffffffu, t, 4);
        if (lane == 0) g_score[node] = tanhf(t + b4[0]);
    }
}

// ---------------- fused tail: sortpool -> conv1+pool -> conv2 ----------------
__global__ void __launch_bounds__(256) k_tail(const float* __restrict__ cw1,
                                              const float* __restrict__ cb1,
                                              const float* __restrict__ cw2,
                                              const float* __restrict__ cb2) {
    __shared__ float s[512];
    __shared__ int   si[512];
    __shared__ float xs[KTOP * TOTALC];   // reused as ps (128*50)
    int g = blockIdx.x, tid = threadIdx.x;

    for (int i = tid; i < 512; i += 256) {
        if (i < NPER) { s[i] = g_score[g * NPER + i]; si[i] = i; }
        else          { s[i] = __int_as_float(0xff800000); si[i] = 0x7FFFFFFF; }
    }
    __syncthreads();
    for (int k = 2; k <= 512; k <<= 1) {
        for (int j = k >> 1; j > 0; j >>= 1) {
            for (int i = tid; i < 512; i += 256) {
                int ixj = i ^ j;
                if (ixj > i) {
                    float a = s[i], bb = s[ixj];
                    int ia = si[i], ib = si[ixj];
                    bool before = (a > bb) || (a == bb && ia < ib);
                    bool dirDesc = ((i & k) == 0);
                    if (dirDesc ? !before : before) {
                        s[i] = bb; s[ixj] = a; si[i] = ib; si[ixj] = ia;
                    }
                }
            }
            __syncthreads();
        }
    }

    for (int i = tid; i < KTOP * TOTALC; i += 256) {
        int kslot = i / TOTALC, t = i - kslot * TOTALC;
        int n = g * NPER + si[kslot];
        float v;
        if (t < 32)      v = g_x1[n * DIMC + t];
        else if (t < 64) v = g_x2[n * DIMC + t - 32];
        else if (t < 96) v = g_x3[n * DIMC + t - 64];
        else             v = g_score[n];
        xs[i] = v;
    }
    __syncthreads();

    float pr[28];
    int nit = 0;
    for (int item = tid; item < 32 * 50; item += 256, nit++) {
        int cb = item / 50, j = item - cb * 50;
        const float* r0 = xs + (2 * j) * TOTALC;
        const float* r1 = r0 + TOTALC;
        float a[8];
#pragma unroll
        for (int q = 0; q < 4; q++) { float bb = cb1[cb + q * 32]; a[q] = bb; a[4 + q] = bb; }
#pragma unroll 2
        for (int t = 0; t < TOTALC; t++) {
            float v0 = r0[t], v1 = r1[t];
#pragma unroll
            for (int q = 0; q < 4; q++) {
                float wv = cw1[(cb + q * 32) * TOTALC + t];
                a[q]     = fmaf(v0, wv, a[q]);
                a[4 + q] = fmaf(v1, wv, a[4 + q]);
            }
        }
#pragma unroll
        for (int q = 0; q < 4; q++)
            pr[nit * 4 + q] = fmaxf(fmaxf(a[q], a[4 + q]), 0.0f);
    }
    __syncthreads();
    float* ps = xs;
    nit = 0;
    for (int item = tid; item < 32 * 50; item += 256, nit++) {
        int cb = item / 50, j = item - cb * 50;
#pragma unroll
        for (int q = 0; q < 4; q++)
            ps[(cb + q * 32) * 50 + j] = pr[nit * 4 + q];
    }
    __syncthreads();

    for (int item = tid; item < 16 * 46; item += 256) {
        int ob = item / 46, j = item - ob * 46;
        float a0 = cb2[ob], a1 = cb2[ob + 16], a2 = cb2[ob + 32], a3 = cb2[ob + 48];
        const float* w0 = cw2 + (ob)      * 640;
        const float* w1 = cw2 + (ob + 16) * 640;
        const float* w2 = cw2 + (ob + 32) * 640;
        const float* w3 = cw2 + (ob + 48) * 640;
#pragma unroll 2
        for (int i = 0; i < 128; i++) {
            const float* pp = ps + i * 50 + j;
            float p0 = pp[0], p1 = pp[1], p2 = pp[2], p3 = pp[3], p4 = pp[4];
            const float* q0 = w0 + i * 5;
            const float* q1 = w1 + i * 5;
            const float* q2 = w2 + i * 5;
            const float* q3 = w3 + i * 5;
            a0 = fmaf(p0, q0[0], a0); a0 = fmaf(p1, q0[1], a0); a0 = fmaf(p2, q0[2], a0);
            a0 = fmaf(p3, q0[3], a0); a0 = fmaf(p4, q0[4], a0);
            a1 = fmaf(p0, q1[0], a1); a1 = fmaf(p1, q1[1], a1); a1 = fmaf(p2, q1[2], a1);
            a1 = fmaf(p3, q1[3], a1); a1 = fmaf(p4, q1[4], a1);
            a2 = fmaf(p0, q2[0], a2); a2 = fmaf(p1, q2[1], a2); a2 = fmaf(p2, q2[2], a2);
            a2 = fmaf(p3, q2[3], a2); a2 = fmaf(p4, q2[4], a2);
            a3 = fmaf(p0, q3[0], a3); a3 = fmaf(p1, q3[1], a3); a3 = fmaf(p2, q3[2], a3);
            a3 = fmaf(p3, q3[3], a3); a3 = fmaf(p4, q3[4], a3);
        }
        g_c2f[g * 2944 + (ob)      * 46 + j] = fmaxf(a0, 0.0f);
        g_c2f[g * 2944 + (ob + 16) * 46 + j] = fmaxf(a1, 0.0f);
        g_c2f[g * 2944 + (ob + 32) * 46 + j] = fmaxf(a2, 0.0f);
        g_c2f[g * 2944 + (ob + 48) * 46 + j] = fmaxf(a3, 0.0f);
    }
}

// ---------------- fc1 + relu + fc3 + log_softmax; zeroes g_cnt for next replay ----------------
__global__ void __launch_bounds__(256) k_fc(const float* __restrict__ fw1,
                                            const float* __restrict__ fb1,
                                            const float* __restrict__ fw3,
                                            const float* __restrict__ fb3,
                                            float* __restrict__ out) {
    __shared__ float cs[4 * 2944];
    __shared__ float part[256];
    int gb = blockIdx.x, tid = threadIdx.x;
    int g0 = gb * 4;
    for (int i = gb * 256 + tid; i < N_NODES; i += gridDim.x * 256) g_cnt[i] = 0;
    for (int i = tid; i < 4 * 2944; i += 256) {
        int g = g0 + i / 2944;
        cs[i] = (g < NGRAPH) ? g_c2f[g * 2944 + (i % 2944)] : 0.0f;
    }
    __syncthreads();
    int half = tid >> 7;
    int o    = tid & 127;
    int dbeg = half * 368;
    const float4* wr = reinterpret_cast<const float4*>(fw1 + (size_t)o * 2944) + dbeg;
    const float4* c0 = reinterpret_cast<const float4*>(cs) + dbeg;
    const float4* c1 = reinterpret_cast<const float4*>(cs + 2944) + dbeg;
    const float4* c2 = reinterpret_cast<const float4*>(cs + 2 * 2944) + dbeg;
    const float4* c3 = reinterpret_cast<const float4*>(cs + 3 * 2944) + dbeg;
    float a0 = 0, a1 = 0, a2 = 0, a3 = 0;
    for (int d = 0; d < 368; d++) {
        float4 w = wr[d];
        float4 v;
        v = c0[d]; a0 += w.x * v.x + w.y * v.y + w.z * v.z + w.w * v.w;
        v = c1[d]; a1 += w.x * v.x + w.y * v.y + w.z * v.z + w.w * v.w;
        v = c2[d]; a2 += w.x * v.x + w.y * v.y + w.z * v.z + w.w * v.w;
        v = c3[d]; a3 += w.x * v.x + w.y * v.y + w.z * v.z + w.w * v.w;
    }
    if (half == 1) { part[o] = a0; part[o + 128] = a1; }
    __syncthreads();
    if (half == 0) { a0 += part[o]; a1 += part[o + 128]; }
    __syncthreads();
    if (half == 1) { part[o] = a2; part[o + 128] = a3; }
    __syncthreads();
    if (half == 0) {
        a2 += part[o]; a3 += part[o + 128];
        float bb = fb1[o];
        cs[0 * 128 + o] = fmaxf(a0 + bb, 0.0f);
        cs[1 * 128 + o] = fmaxf(a1 + bb, 0.0f);
        cs[2 * 128 + o] = fmaxf(a2 + bb, 0.0f);
        cs[3 * 128 + o] = fmaxf(a3 + bb, 0.0f);
    }
    __syncthreads();
    int wid = tid >> 5, lane = tid & 31;
    if (wid < 4 && g0 + wid < NGRAPH) {
        float l0 = 0.f, l1 = 0.f;
#pragma unroll
        for (int k = 0; k < 4; k++) {
            int d = lane + 32 * k;
            float h = cs[wid * 128 + d];
            l0 = fmaf(h, fw3[d], l0);
            l1 = fmaf(h, fw3[128 + d], l1);
        }
#pragma unroll
        for (int off = 16; off; off >>= 1) {
            l0 += __shfl_xor_sync(0xffffffffu, l0, off);
            l1 += __shfl_xor_sync(0xffffffffu, l1, off);
        }
        if (lane == 0) {
            l0 += fb3[0]; l1 += fb3[1];
            float m = fmaxf(l0, l1);
            float lse = m + logf(expf(l0 - m) + expf(l1 - m));
            out[(g0 + wid) * 2 + 0] = l0 - lse;
            out[(g0 + wid) * 2 + 1] = l1 - lse;
        }
    }
}

// ---------------- launch ----------------
extern "C" void kernel_launch(void* const* d_in, const int* in_sizes, int n_in,
                              void* d_out, int out_size) {
    const float* x   = (const float*)d_in[0];
    const int*   ei  = (const int*)d_in[1];
    const int*   src = ei;
    const int*   dst = ei + N_EDGES;
    const float* W1 = (const float*)d_in[3];  const float* b1 = (const float*)d_in[4];
    const float* W2 = (const float*)d_in[5];  const float* b2 = (const float*)d_in[6];
    const float* W3 = (const float*)d_in[7];  const float* b3 = (const float*)d_in[8];
    const float* W4 = (const float*)d_in[9];  const float* b4 = (const float*)d_in[10];
    const float* cw1 = (const float*)d_in[11]; const float* cb1 = (const float*)d_in[12];
    const float* cw2 = (const float*)d_in[13]; const float* cb2 = (const float*)d_in[14];
    const float* fw1 = (const float*)d_in[15]; const float* fb1 = (const float*)d_in[16];
    const float* fw3 = (const float*)d_in[17]; const float* fb3 = (const float*)d_in[18];
    float* out = (float*)d_out;

    const int TB = 256;
    const int gG8 = (N_NODES + 7) / 8;           // 12500

    k_fillb<<<N_EDGES / 4 / TB, TB>>>(src, dst);                  // 0 (hist+fill in one)
    k_gemm1<<<(N_NODES + GM1_NODES - 1) / GM1_NODES, TB>>>(x, W1);// 1 (dis + pad8)
    k_gather<<<gG8, TB>>>(1, nullptr, b1, nullptr, nullptr);      // 2
    k_gather<<<gG8, TB>>>(2, W2, b2, nullptr, nullptr);           // 3 <- profiled
    k_gather<<<gG8, TB>>>(3, W3, b3, W4, b4);                     // 4
    k_tail<<<NGRAPH, TB>>>(cw1, cb1, cw2, cb2);                   // 5
    k_fc<<<(NGRAPH + 3) / 4, TB>>>(fw1, fb1, fw3, fb3, out);      // 6
}